// round 5
// baseline (speedup 1.0000x reference)
#include <cuda_runtime.h>

#define B_ 8
#define C_ 256
#define H_ 128
#define W_ 128
#define HW_ (H_*W_)
#define NPIX (B_*HW_)

#define CG16 16          // conv channel groups
#define CPG16 (C_/CG16)  // 16 channels per group
#define RT 16            // output rows per conv block

#define TH 8             // sampler: output rows per block
#define CS4 4            // sampler channel splits
#define CPB (C_/CS4)     // 64 channels per sampler block
#define RMAX 28          // max staged rows
#define NTS 512          // sampler threads

__device__ float2 g_part[CG16 * NPIX];   // conv partials
__device__ float2 g_off[NPIX];           // merged offsets

__device__ __forceinline__ unsigned long long pack2(float v) {
    unsigned long long r;
    asm("mov.b64 %0, {%1, %1};" : "=l"(r) : "f"(v));
    return r;
}
__device__ __forceinline__ void ffma2(unsigned long long& d,
                                      unsigned long long a,
                                      unsigned long long b) {
    asm("fma.rn.f32x2 %0, %1, %2, %0;" : "+l"(d) : "l"(a), "l"(b));
}
__device__ __forceinline__ void unpack2(unsigned long long v, float& lo, float& hi) {
    asm("mov.b64 {%0, %1}, %2;" : "=f"(lo), "=f"(hi) : "l"(v));
}

// ---------------------------------------------------------------------------
// Kernel 1 (r3 form): offset conv partials, f32x2 packed, shuffle halos.
// Grid: B_*(H_/RT)*CG16 = 1024 blocks, 128 threads.
// ---------------------------------------------------------------------------
__global__ __launch_bounds__(128) void conv_kernel(const float* __restrict__ x,
                                                   const float* __restrict__ wc) {
    const int lane = threadIdx.x & 31;
    const int wrp  = threadIdx.x >> 5;
    int bx = blockIdx.x;
    const int g  = bx & 15; bx >>= 4;
    const int hb = bx & 7;  bx >>= 3;
    const int b  = bx;
    const int h0   = hb * RT + wrp * 4;
    const int c0   = g * CPG16;
    const int col0 = lane * 4;

    __shared__ float2 swp[CPG16 * 9];
    for (int i = threadIdx.x; i < CPG16 * 9; i += 128)
        swp[i] = make_float2(wc[c0 * 9 + i], wc[C_ * 9 + c0 * 9 + i]);
    __syncthreads();

    unsigned long long acc[4][4];
#pragma unroll
    for (int r = 0; r < 4; r++)
#pragma unroll
        for (int j = 0; j < 4; j++) acc[r][j] = 0ull;

    const float* xb = x + (size_t)(b * C_ + c0) * HW_;

#pragma unroll 1
    for (int c = 0; c < CPG16; c++) {
        const float* xc = xb + c * HW_;
        float4 f[6];
#pragma unroll
        for (int r = 0; r < 6; r++) {
            const int hr = h0 - 1 + r;
            if (hr >= 0 && hr < H_) f[r] = *(const float4*)(xc + hr * W_ + col0);
            else                    f[r] = make_float4(0.f, 0.f, 0.f, 0.f);
        }

        float colv[6][6];
#pragma unroll
        for (int r = 0; r < 6; r++) {
            float lh = __shfl_up_sync(0xffffffffu, f[r].w, 1);
            float rh = __shfl_down_sync(0xffffffffu, f[r].x, 1);
            if (lane == 0)  lh = 0.f;
            if (lane == 31) rh = 0.f;
            colv[r][0] = lh;   colv[r][1] = f[r].x; colv[r][2] = f[r].y;
            colv[r][3] = f[r].z; colv[r][4] = f[r].w; colv[r][5] = rh;
        }

        unsigned long long wp[9];
#pragma unroll
        for (int k = 0; k < 9; k++)
            wp[k] = *(const unsigned long long*)&swp[c * 9 + k];

#pragma unroll
        for (int ri = 0; ri < 6; ri++)
#pragma unroll
            for (int ci = 0; ci < 6; ci++) {
                const unsigned long long v2 = pack2(colv[ri][ci]);
#pragma unroll
                for (int kh = 0; kh < 3; kh++) {
                    const int rr = ri - kh;
                    if (rr < 0 || rr > 3) continue;
#pragma unroll
                    for (int kw = 0; kw < 3; kw++) {
                        const int j = ci - kw;
                        if (j < 0 || j > 3) continue;
                        ffma2(acc[rr][j], wp[kh * 3 + kw], v2);
                    }
                }
            }
    }

    float2* gp = g_part + (size_t)g * NPIX + b * HW_;
#pragma unroll
    for (int rr = 0; rr < 4; rr++)
#pragma unroll
        for (int j = 0; j < 4; j++) {
            float axv, ayv;
            unpack2(acc[rr][j], axv, ayv);
            gp[(h0 + rr) * W_ + col0 + j] = make_float2(axv, ayv);
        }
}

// ---------------------------------------------------------------------------
// Kernel 1.5: merge the 16 partials.
// ---------------------------------------------------------------------------
__global__ __launch_bounds__(256) void reduce_kernel() {
    const int i = blockIdx.x * 256 + threadIdx.x;
    float ox = 0.f, oy = 0.f;
#pragma unroll
    for (int g = 0; g < CG16; g++) {
        const float2 p = g_part[(size_t)g * NPIX + i];
        ox += p.x; oy += p.y;
    }
    g_off[i] = make_float2(ox, oy);
}

// ---------------------------------------------------------------------------
// Kernel 2: smem-staged bilinear gather.
// Block: TH=8 output rows x 128 cols, 64 channels (CS4 split). 512 threads,
// 2 pixels/thread. Per channel: coalesced float4 staging of the needed row
// band into double-buffered smem, then 4 conflict-free LDS per pixel.
// Grid: (cs fastest) B_*(H_/TH)*CS4 = 512 blocks.
// ---------------------------------------------------------------------------
__global__ __launch_bounds__(NTS) void sample_kernel(const float* __restrict__ x,
                                                     const float* __restrict__ bc,
                                                     float* __restrict__ out) {
    __shared__ float sbuf[2][RMAX * 128];
    __shared__ int swmin[16], swmax[16];
    __shared__ int s_qlo, s_qhi;

    const int tid = threadIdx.x;
    int bx = blockIdx.x;
    const int cs = bx & 3;  bx >>= 2;
    const int ht = bx & 15; bx >>= 4;
    const int b  = bx;
    const int h0 = ht * TH;
    const float bc0 = bc[0], bc1 = bc[1];

    // two pixels per thread: p and p+512 within the 8x128 tile
    int   qx[2], qy[2], sa[2];
    float w00[2], w01[2], w10[2], w11[2];
    float* op[2];

#pragma unroll
    for (int k = 0; k < 2; k++) {
        const int p = tid + k * NTS;
        const int r = p >> 7;
        const int w = p & 127;
        const int h = h0 + r;
        const float2 o = g_off[(b * H_ + h) * W_ + w];
        float px = (float)h + o.x + bc0;
        float py = (float)w + o.y + bc1;
        px = fminf(fmaxf(px, 0.f), (float)(H_ - 2));
        py = fminf(fmaxf(py, 0.f), (float)(W_ - 2));
        const float fx = floorf(px), fy = floorf(py);
        const float dx = px - fx,    dy = py - fy;
        w00[k] = (1.f - dx) * (1.f - dy);
        w01[k] = (1.f - dx) * dy;
        w10[k] = dx * (1.f - dy);
        w11[k] = dx * dy;
        qx[k] = (int)fx; qy[k] = (int)fy;
        op[k] = out + ((size_t)(b * C_ + cs * CPB)) * HW_ + h * W_ + w;
    }

    // block-wide min/max of qx
    int mn = min(qx[0], qx[1]);
    int mx = max(qx[0], qx[1]);
    mn = __reduce_min_sync(0xffffffffu, mn);
    mx = __reduce_max_sync(0xffffffffu, mx);
    if ((tid & 31) == 0) { swmin[tid >> 5] = mn; swmax[tid >> 5] = mx; }
    __syncthreads();
    if (tid == 0) {
        int a = swmin[0], z = swmax[0];
#pragma unroll
        for (int i = 1; i < 16; i++) { a = min(a, swmin[i]); z = max(z, swmax[i]); }
        s_qlo = a; s_qhi = z;
    }
    __syncthreads();
    const int qlo = s_qlo;
    const int R   = s_qhi + 2 - qlo;     // staged rows qlo .. qhi+1

    const float* xc0 = x + ((size_t)(b * C_ + cs * CPB)) * HW_;

    if (R <= RMAX) {
#pragma unroll
        for (int k = 0; k < 2; k++) sa[k] = (qx[k] - qlo) * 128 + qy[k];

        const int nf4   = R * 32;            // float4 count to stage
        const int i0    = tid;
        const int i1    = tid + NTS;
        const bool v1   = (i1 < nf4);        // i0 < 512 <= nf4 only if R>=16
        const bool v0   = (i0 < nf4);
        const int ga0   = (qlo + (i0 >> 5)) * W_ + (i0 & 31) * 4;
        const int ga1   = (qlo + (i1 >> 5)) * W_ + (i1 & 31) * 4;

        // stage channel 0
        {
            const float* xc = xc0;
            if (v0) *(float4*)&sbuf[0][i0 * 4] = __ldg((const float4*)(xc + ga0));
            if (v1) *(float4*)&sbuf[0][i1 * 4] = __ldg((const float4*)(xc + ga1));
        }
        __syncthreads();

#pragma unroll 1
        for (int c = 0; c < CPB; c++) {
            const int cur = c & 1;
            float4 n0, n1;
            if (c + 1 < CPB) {               // prefetch next channel's band
                const float* xc = xc0 + (size_t)(c + 1) * HW_;
                if (v0) n0 = __ldg((const float4*)(xc + ga0));
                if (v1) n1 = __ldg((const float4*)(xc + ga1));
            }

            const float* sb = sbuf[cur];
#pragma unroll
            for (int k = 0; k < 2; k++) {
                const float v00 = sb[sa[k]];
                const float v01 = sb[sa[k] + 1];
                const float v10 = sb[sa[k] + 128];
                const float v11 = sb[sa[k] + 129];
                op[k][(size_t)c * HW_] =
                    fmaf(w00[k], v00, fmaf(w01[k], v01,
                    fmaf(w10[k], v10, w11[k] * v11)));
            }

            if (c + 1 < CPB) {
                if (v0) *(float4*)&sbuf[cur ^ 1][i0 * 4] = n0;
                if (v1) *(float4*)&sbuf[cur ^ 1][i1 * 4] = n1;
            }
            __syncthreads();
        }
    } else {
        // fallback: direct gather (rare; correctness safety net)
#pragma unroll 1
        for (int c = 0; c < CPB; c++) {
            const float* xc = xc0 + (size_t)c * HW_;
#pragma unroll
            for (int k = 0; k < 2; k++) {
                const float* p = xc + qx[k] * W_ + qy[k];
                const float v00 = __ldg(p);
                const float v01 = __ldg(p + 1);
                const float v10 = __ldg(p + W_);
                const float v11 = __ldg(p + W_ + 1);
                op[k][(size_t)c * HW_] =
                    fmaf(w00[k], v00, fmaf(w01[k], v01,
                    fmaf(w10[k], v10, w11[k] * v11)));
            }
        }
    }
}

// ---------------------------------------------------------------------------
extern "C" void kernel_launch(void* const* d_in, const int* in_sizes, int n_in,
                              void* d_out, int out_size) {
    const float* x  = (const float*)d_in[0];   // [8,256,128,128]
    const float* wc = (const float*)d_in[1];   // [2,256,3,3]
    const float* bc = (const float*)d_in[2];   // [2]
    float* out = (float*)d_out;                // [8,256,128,128,1]

    conv_kernel<<<B_ * (H_ / RT) * CG16, 128>>>(x, wc);
    reduce_kernel<<<NPIX / 256, 256>>>();
    sample_kernel<<<B_ * (H_ / TH) * CS4, NTS>>>(x, bc, out);
}

// round 6
// speedup vs baseline: 1.2296x; 1.2296x over previous
#include <cuda_runtime.h>

#define B_ 8
#define C_ 256
#define H_ 128
#define W_ 128
#define HW_ (H_*W_)
#define NPIX (B_*HW_)

#define CG 32            // conv channel groups
#define CPG (C_/CG)      // 8 channels per group
#define RT 16            // output rows per conv block

#define CSPLIT 4
#define CPS (C_/CSPLIT)

__device__ float2 g_part[CG * NPIX];     // conv partials (33.5 MB)
__device__ float2 g_off[NPIX];           // merged offsets

__device__ __forceinline__ unsigned long long pack2(float v) {
    unsigned long long r;
    asm("mov.b64 %0, {%1, %1};" : "=l"(r) : "f"(v));
    return r;
}
__device__ __forceinline__ void ffma2(unsigned long long& d,
                                      unsigned long long a,
                                      unsigned long long b) {
    asm("fma.rn.f32x2 %0, %1, %2, %0;" : "+l"(d) : "l"(a), "l"(b));
}
__device__ __forceinline__ void unpack2(unsigned long long v, float& lo, float& hi) {
    asm("mov.b64 {%0, %1}, %2;" : "=f"(lo), "=f"(hi) : "l"(v));
}

// ---------------------------------------------------------------------------
// Kernel 1: offset conv partials, f32x2 packed, shuffle halos, no inner
// barriers. Grid: B_*(H_/RT)*CG = 2048 blocks, 128 threads.
// ---------------------------------------------------------------------------
__global__ __launch_bounds__(128) void conv_kernel(const float* __restrict__ x,
                                                   const float* __restrict__ wc) {
    const int lane = threadIdx.x & 31;
    const int wrp  = threadIdx.x >> 5;
    int bx = blockIdx.x;
    const int g  = bx & 31; bx >>= 5;
    const int hb = bx & 7;  bx >>= 3;
    const int b  = bx;
    const int h0   = hb * RT + wrp * 4;
    const int c0   = g * CPG;
    const int col0 = lane * 4;

    __shared__ float2 swp[CPG * 9];
    for (int i = threadIdx.x; i < CPG * 9; i += 128)
        swp[i] = make_float2(wc[c0 * 9 + i], wc[C_ * 9 + c0 * 9 + i]);
    __syncthreads();

    unsigned long long acc[4][4];
#pragma unroll
    for (int r = 0; r < 4; r++)
#pragma unroll
        for (int j = 0; j < 4; j++) acc[r][j] = 0ull;

    const float* xb = x + (size_t)(b * C_ + c0) * HW_;

#pragma unroll 1
    for (int c = 0; c < CPG; c++) {
        const float* xc = xb + c * HW_;
        float4 f[6];
#pragma unroll
        for (int r = 0; r < 6; r++) {
            const int hr = h0 - 1 + r;
            if (hr >= 0 && hr < H_) f[r] = *(const float4*)(xc + hr * W_ + col0);
            else                    f[r] = make_float4(0.f, 0.f, 0.f, 0.f);
        }

        float colv[6][6];
#pragma unroll
        for (int r = 0; r < 6; r++) {
            float lh = __shfl_up_sync(0xffffffffu, f[r].w, 1);
            float rh = __shfl_down_sync(0xffffffffu, f[r].x, 1);
            if (lane == 0)  lh = 0.f;
            if (lane == 31) rh = 0.f;
            colv[r][0] = lh;   colv[r][1] = f[r].x; colv[r][2] = f[r].y;
            colv[r][3] = f[r].z; colv[r][4] = f[r].w; colv[r][5] = rh;
        }

        unsigned long long wp[9];
#pragma unroll
        for (int k = 0; k < 9; k++)
            wp[k] = *(const unsigned long long*)&swp[c * 9 + k];

#pragma unroll
        for (int ri = 0; ri < 6; ri++)
#pragma unroll
            for (int ci = 0; ci < 6; ci++) {
                const unsigned long long v2 = pack2(colv[ri][ci]);
#pragma unroll
                for (int kh = 0; kh < 3; kh++) {
                    const int rr = ri - kh;
                    if (rr < 0 || rr > 3) continue;
#pragma unroll
                    for (int kw = 0; kw < 3; kw++) {
                        const int j = ci - kw;
                        if (j < 0 || j > 3) continue;
                        ffma2(acc[rr][j], wp[kh * 3 + kw], v2);
                    }
                }
            }
    }

    float2* gp = g_part + (size_t)g * NPIX + b * HW_;
#pragma unroll
    for (int rr = 0; rr < 4; rr++)
#pragma unroll
        for (int j = 0; j < 4; j++) {
            float axv, ayv;
            unpack2(acc[rr][j], axv, ayv);
            gp[(h0 + rr) * W_ + col0 + j] = make_float2(axv, ayv);
        }
}

// ---------------------------------------------------------------------------
// Kernel 1.5: merge the 32 partials.
// ---------------------------------------------------------------------------
__global__ __launch_bounds__(256) void reduce_kernel() {
    const int i = blockIdx.x * 256 + threadIdx.x;
    float ox = 0.f, oy = 0.f;
#pragma unroll
    for (int g = 0; g < CG; g++) {
        const float2 p = g_part[(size_t)g * NPIX + i];
        ox += p.x; oy += p.y;
    }
    g_off[i] = make_float2(ox, oy);
}

// ---------------------------------------------------------------------------
// Kernel 2: bilinear gather (r2 form: 4 scalar __ldg, no divergence).
// Grid: B_*H_*CSPLIT = 4096 blocks, 128 threads.
// ---------------------------------------------------------------------------
__global__ __launch_bounds__(128) void sample_kernel(const float* __restrict__ x,
                                                     const float* __restrict__ bc,
                                                     float* __restrict__ out) {
    const int w = threadIdx.x;
    int bx = blockIdx.x;
    const int s = bx & (CSPLIT - 1); bx >>= 2;
    const int h = bx & (H_ - 1);
    const int b = bx >> 7;
    const int pix = (b * H_ + h) * W_ + w;

    const float2 o = g_off[pix];
    float px = (float)h + o.x + bc[0];
    float py = (float)w + o.y + bc[1];
    px = fminf(fmaxf(px, 0.f), (float)(H_ - 2));
    py = fminf(fmaxf(py, 0.f), (float)(W_ - 2));

    const float fx = floorf(px), fy = floorf(py);
    const float dx = px - fx,    dy = py - fy;
    const float w00 = (1.f - dx) * (1.f - dy);
    const float w01 = (1.f - dx) * dy;
    const float w10 = dx * (1.f - dy);
    const float w11 = dx * dy;

    const int qx = (int)fx, qy = (int)fy;
    const float* xp = x   + ((size_t)b * C_ + s * CPS) * HW_ + qx * W_ + qy;
    float*       op = out + ((size_t)b * C_ + s * CPS) * HW_ + h * W_ + w;

#pragma unroll 8
    for (int c = 0; c < CPS; c++) {
        const float* p = xp + c * HW_;
        const float v00 = __ldg(p);
        const float v01 = __ldg(p + 1);
        const float v10 = __ldg(p + W_);
        const float v11 = __ldg(p + W_ + 1);
        op[c * HW_] = fmaf(w00, v00, fmaf(w01, v01, fmaf(w10, v10, w11 * v11)));
    }
}

// ---------------------------------------------------------------------------
extern "C" void kernel_launch(void* const* d_in, const int* in_sizes, int n_in,
                              void* d_out, int out_size) {
    const float* x  = (const float*)d_in[0];   // [8,256,128,128]
    const float* wc = (const float*)d_in[1];   // [2,256,3,3]
    const float* bc = (const float*)d_in[2];   // [2]
    float* out = (float*)d_out;                // [8,256,128,128,1]

    conv_kernel<<<B_ * (H_ / RT) * CG, 128>>>(x, wc);
    reduce_kernel<<<NPIX / 256, 256>>>();
    sample_kernel<<<B_ * H_ * CSPLIT, 128>>>(x, bc, out);
}